// round 15
// baseline (speedup 1.0000x reference)
#include <cuda_runtime.h>

#define BB    4
#define NN    100000
#define MM    64
#define HM    32           // half of MM
#define TPB   256
#define BPI   148          // grid = 148*4 = 592 = 148 SMs * 4 CTAs (one wave)
#define CHUNK 676          // ceil(100000/148) = 676 = 2*256 + 164
#define REM   (CHUNK - 2 * TPB)   // 164

// Intersection + C = (S + Ap), bit-exact op order vs reference
// (clamp-after-sub; S = (z-x)*(w-y) rounded like the reference; C = S + Ap).
// S is recomputed from g here (fma-pipe) instead of a second shared-mem load.
__device__ __forceinline__ void iou_ic(const float4 g, const float S,
                                       const float4 p, const float Ap,
                                       float& inter, float& C)
{
    const float ltx = fmaxf(g.x, p.x);
    const float lty = fmaxf(g.y, p.y);
    const float rbx = fminf(g.z, p.z);
    const float rby = fminf(g.w, p.w);
    const float wx  = fmaxf(__fsub_rn(rbx, ltx), 0.0f);
    const float wy  = fmaxf(__fsub_rn(rby, lty), 0.0f);
    inter = __fmul_rn(wx, wy);
    C     = __fadd_rn(S, Ap);
}

__device__ __forceinline__ float area_of(const float4 b) {
    return __fmul_rn(__fsub_rn(b.z, b.x), __fsub_rn(b.w, b.y));
}

struct Best { float I, C; int i; };

// r_new > r_best  <=>  in * b.C > b.I * C   (C > 0); strict > keeps first max.
__device__ __forceinline__ void upd(Best& b, const float in, const float C, const int i)
{
    const bool t = __fmul_rn(in, b.C) > __fmul_rn(b.I, C);
    b.I = t ? in : b.I;
    b.C = t ? C  : b.C;
    b.i = t ? i  : b.i;
}

// Merge two half-range bests: upper half wins only on STRICT greater (first-max-wins).
__device__ __forceinline__ Best merge(const Best lo, const Best hi)
{
    const bool t = __fmul_rn(hi.I, lo.C) > __fmul_rn(lo.I, hi.C);
    Best w;
    w.I = t ? hi.I : lo.I;
    w.C = t ? hi.C : lo.C;
    w.i = t ? hi.i : lo.i;
    return w;
}

// Encode targets + decode deltas + write all three outputs for one proposal.
__device__ __forceinline__ void epilogue(const float4 p, const float4 d, const float4 mg,
                                         const int match, const int idx,
                                         float* __restrict__ out)
{
    const float aw = p.z - p.x;
    const float ah = p.w - p.y;
    const float ax = p.x + 0.5f * aw;
    const float ay = p.y + 0.5f * ah;
    const float rw = __fdividef(1.0f, aw);   // fast rcp: outputs only need 1e-3
    const float rh = __fdividef(1.0f, ah);

    const float gw = fmaxf(mg.z - mg.x, 1.0f);
    const float gh = fmaxf(mg.w - mg.y, 1.0f);
    const float gx = mg.x + 0.5f * gw;
    const float gy = mg.y + 0.5f * gh;

    float4 tgt;
    tgt.x = (gx - ax) * rw * 10.0f;   // / 0.1
    tgt.y = (gy - ay) * rh * 10.0f;
    tgt.z = __logf(gw * rw) * 5.0f;   // / 0.2
    tgt.w = __logf(gh * rh) * 5.0f;

    const float cx = ax + (d.x * 0.1f) * aw;
    const float cy = ay + (d.y * 0.1f) * ah;
    const float pw = __expf(d.z * 0.2f) * aw;
    const float ph = __expf(d.w * 0.2f) * ah;

    float4 dec;
    dec.x = cx - 0.5f * pw;
    dec.y = cy - 0.5f * ph;
    dec.z = cx + 0.5f * pw;
    dec.w = cy + 0.5f * ph;

    ((float4*)out)[idx] = dec;                       // decoded  [B,N,4]
    ((float4*)(out + 4 * BB * NN))[idx] = tgt;       // targets  [B,N,4]
    (out + 8 * BB * NN)[idx] = (float)match;         // matches  [B,N]
}

// Single-proposal matcher (2 half-streams) + epilogue; used by remainder lanes.
__device__ __forceinline__ void process_one(const float4* __restrict__ prop_b,
                                            const float4* __restrict__ del_b,
                                            const float4* __restrict__ sg,
                                            const int n, const int bofs,
                                            float* __restrict__ out)
{
    const float4 p  = prop_b[n];
    const float  Ap = area_of(p);

    Best a, c;
    {
        const float4 gl = sg[0];
        const float4 gh = sg[HM];
        iou_ic(gl, area_of(gl), p, Ap, a.I, a.C); a.i = 0;
        iou_ic(gh, area_of(gh), p, Ap, c.I, c.C); c.i = HM;
    }

    #pragma unroll 4
    for (int k = 1; k < HM; k++) {
        const float4 gl = sg[k];
        const float4 gh = sg[HM + k];
        float in, Cc;
        iou_ic(gl, area_of(gl), p, Ap, in, Cc); upd(a, in, Cc, k);
        iou_ic(gh, area_of(gh), p, Ap, in, Cc); upd(c, in, Cc, HM + k);
    }

    const Best w = merge(a, c);
    const float denom = __fsub_rn(w.C, w.I);         // == reference's rounded denom
    const float iou   = __fdiv_rn(w.I, denom);       // exact -> threshold bit-faithful
    const int   m     = (iou < 0.5f) ? -1 : w.i;
    const float4 mg   = sg[(m < 0) ? 0 : w.i];
    epilogue(p, del_b[n], mg, m, bofs + n, out);
}

__global__ __launch_bounds__(TPB, 4)
void roihead_kernel(const float4* __restrict__ proposals,
                    const float4* __restrict__ gt,
                    const float4* __restrict__ deltas,
                    float* __restrict__ out)
{
    __shared__ float4 sg[MM];

    const int b   = blockIdx.y;
    const int tid = threadIdx.x;

    if (tid < MM)
        sg[tid] = gt[b * MM + tid];
    __syncthreads();

    const int base = blockIdx.x * CHUNK;
    const int bofs = b * NN;
    const float4* prop_b = proposals + bofs;
    const float4* del_b  = deltas    + bofs;

    // ---- pair phase: 2 proposals/thread x 2 gt-halves = 4 independent argmax
    //      streams; one LDS.128 per gt serves both proposals, S recomputed on fma pipe.
    //      No bounds checks: max index = 147*676 + 511 = 99883 < 100000.
    {
        const int n0 = base + tid;
        const int n1 = base + TPB + tid;

        const float4 p0 = proposals[bofs + n0];
        const float4 p1 = proposals[bofs + n1];
        const float Ap0 = area_of(p0);
        const float Ap1 = area_of(p1);

        Best a0, c0, a1, c1;
        {
            const float4 gl = sg[0];  const float Sl = area_of(gl);
            const float4 gh = sg[HM]; const float Sh = area_of(gh);
            iou_ic(gl, Sl, p0, Ap0, a0.I, a0.C); a0.i = 0;
            iou_ic(gl, Sl, p1, Ap1, a1.I, a1.C); a1.i = 0;
            iou_ic(gh, Sh, p0, Ap0, c0.I, c0.C); c0.i = HM;
            iou_ic(gh, Sh, p1, Ap1, c1.I, c1.C); c1.i = HM;
        }

        #pragma unroll 4
        for (int k = 1; k < HM; k++) {
            const float4 gl = sg[k];      const float Sl = area_of(gl);
            const float4 gh = sg[HM + k]; const float Sh = area_of(gh);

            float in, Cc;
            iou_ic(gl, Sl, p0, Ap0, in, Cc); upd(a0, in, Cc, k);
            iou_ic(gl, Sl, p1, Ap1, in, Cc); upd(a1, in, Cc, k);
            iou_ic(gh, Sh, p0, Ap0, in, Cc); upd(c0, in, Cc, HM + k);
            iou_ic(gh, Sh, p1, Ap1, in, Cc); upd(c1, in, Cc, HM + k);
        }

        const Best w0 = merge(a0, c0);
        const Best w1 = merge(a1, c1);

        const float dn0  = __fsub_rn(w0.C, w0.I);    // reference-rounded denominators
        const float dn1  = __fsub_rn(w1.C, w1.I);
        const float iou0 = __fdiv_rn(w0.I, dn0);     // exact winner division
        const float iou1 = __fdiv_rn(w1.I, dn1);

        // FG_THRESH == BG_THRESH == 0.5 -> BETWEEN(-2) unreachable.
        const int m0 = (iou0 < 0.5f) ? -1 : w0.i;
        const int m1 = (iou1 < 0.5f) ? -1 : w1.i;

        const float4 mg0 = sg[(m0 < 0) ? 0 : w0.i];  // jnp.clip(matches, 0) gather
        const float4 mg1 = sg[(m1 < 0) ? 0 : w1.i];

        epilogue(p0, del_b[n0], mg0, m0, bofs + n0, out);
        epilogue(p1, del_b[n1], mg1, m1, bofs + n1, out);
    }

    // ---- remainder phase: 164 lanes handle one more proposal each ----
    if (tid < REM) {
        const int n2 = base + 2 * TPB + tid;
        if (n2 < NN)
            process_one(prop_b, del_b, sg, n2, bofs, out);
    }
}

extern "C" void kernel_launch(void* const* d_in, const int* in_sizes, int n_in,
                              void* d_out, int out_size)
{
    const float4* proposals = (const float4*)d_in[0];
    const float4* gt        = (const float4*)d_in[1];
    const float4* deltas    = (const float4*)d_in[2];
    float* out = (float*)d_out;

    dim3 grid(BPI, BB);
    roihead_kernel<<<grid, TPB>>>(proposals, gt, deltas, out);
}